// round 1
// baseline (speedup 1.0000x reference)
#include <cuda_runtime.h>
#include <math.h>

#define DD 128
#define VOL (DD*DD*DD)
#define NSL 16
#define NPIX (NSL*DD*DD)
#define RED_BLOCKS 1024
#define RED_THREADS 256
#define CG_ITER 10

// ---------------- device scratch (no allocations allowed) ----------------
__device__ float g_x[VOL];
__device__ float g_r[VOL];
__device__ float g_p[VOL];
__device__ float g_Ap[VOL];
__device__ float g_b[VOL];
__device__ float g_part[RED_BLOCKS];
__device__ float g_scal[4];   // [0]=rr, [1]=alpha, [2]=beta

// ---------------- elementwise helpers ----------------
__global__ void k_zero(float* __restrict__ v, int n) {
    int i = blockIdx.x * blockDim.x + threadIdx.x;
    if (i < n) v[i] = 0.f;
}
__global__ void k_copy(float* __restrict__ d, const float* __restrict__ s, int n) {
    int i = blockIdx.x * blockDim.x + threadIdx.x;
    if (i < n) d[i] = s[i];
}
// r = b - Ap ; p = r
__global__ void k_rp0(float* __restrict__ r, float* __restrict__ p,
                      const float* __restrict__ b, const float* __restrict__ Ap, int n) {
    int i = blockIdx.x * blockDim.x + threadIdx.x;
    if (i < n) { float v = b[i] - Ap[i]; r[i] = v; p[i] = v; }
}
// x += alpha*p ; r -= alpha*Ap   (alpha = scal[1])
__global__ void k_xr(float* __restrict__ x, float* __restrict__ r,
                     const float* __restrict__ p, const float* __restrict__ Ap,
                     const float* __restrict__ scal, int n) {
    int i = blockIdx.x * blockDim.x + threadIdx.x;
    if (i < n) {
        float a = __ldg(scal + 1);
        x[i] = fmaf(a, p[i], x[i]);
        r[i] = fmaf(-a, Ap[i], r[i]);
    }
}
// p = r + beta*p   (beta = scal[2])
__global__ void k_updp(float* __restrict__ p, const float* __restrict__ r,
                       const float* __restrict__ scal, int n) {
    int i = blockIdx.x * blockDim.x + threadIdx.x;
    if (i < n) {
        float bta = __ldg(scal + 2);
        p[i] = fmaf(bta, p[i], r[i]);
    }
}
__global__ void k_relu(float* __restrict__ o, const float* __restrict__ x, int n) {
    int i = blockIdx.x * blockDim.x + threadIdx.x;
    if (i < n) o[i] = fmaxf(x[i], 0.f);
}

// ---------------- deterministic two-stage dot product ----------------
__global__ void k_dot(const float* __restrict__ a, const float* __restrict__ b,
                      float* __restrict__ part) {
    __shared__ float sh[RED_THREADS];
    float s = 0.f;
    for (int i = blockIdx.x * RED_THREADS + threadIdx.x; i < VOL;
         i += RED_BLOCKS * RED_THREADS)
        s = fmaf(a[i], b[i], s);
    sh[threadIdx.x] = s;
    __syncthreads();
    for (int o = RED_THREADS / 2; o > 0; o >>= 1) {
        if (threadIdx.x < o) sh[threadIdx.x] += sh[threadIdx.x + o];
        __syncthreads();
    }
    if (threadIdx.x == 0) part[blockIdx.x] = sh[0];
}

// mode 0: rr = sum
// mode 1: alpha = rr / sum      (sum = p.Ap)
// mode 2: beta = sum / rr ; rr = sum   (sum = rr_new)
__global__ void k_final(const float* __restrict__ part, float* __restrict__ scal, int mode) {
    __shared__ float sh[RED_BLOCKS];
    int t = threadIdx.x;
    sh[t] = part[t];
    __syncthreads();
    for (int o = RED_BLOCKS / 2; o > 0; o >>= 1) {
        if (t < o) sh[t] += sh[t + o];
        __syncthreads();
    }
    if (t == 0) {
        float s = sh[0];
        if (mode == 0)      { g_scal[0] = s; }
        else if (mode == 1) { g_scal[1] = g_scal[0] / s; }
        else                { g_scal[2] = s / g_scal[0]; g_scal[0] = s; }
        (void)scal;
    }
}

// ---------------- trilinear gather / scatter (exact mirror of reference) ----------------
__device__ __forceinline__ float tri_gather(const float* __restrict__ vol,
                                            float x, float y, float z) {
    float x0f = floorf(x), y0f = floorf(y), z0f = floorf(z);
    float fx = x - x0f, fy = y - y0f, fz = z - z0f;
    int x0 = (int)x0f, y0 = (int)y0f, z0 = (int)z0f;
    float v = 0.f;
#pragma unroll
    for (int dz = 0; dz < 2; dz++) {
        int zi = z0 + dz;
        if (zi < 0 || zi >= DD) continue;
        float wz = dz ? fz : 1.f - fz;
#pragma unroll
        for (int dy = 0; dy < 2; dy++) {
            int yi = y0 + dy;
            if (yi < 0 || yi >= DD) continue;
            float wzy = wz * (dy ? fy : 1.f - fy);
            int base = (zi << 14) + (yi << 7);
#pragma unroll
            for (int dx = 0; dx < 2; dx++) {
                int xi = x0 + dx;
                if (xi < 0 || xi >= DD) continue;
                float w = wzy * (dx ? fx : 1.f - fx);
                v = fmaf(w, __ldg(vol + base + xi), v);
            }
        }
    }
    return v;
}

__device__ __forceinline__ void tri_scatter(float* __restrict__ vol,
                                            float x, float y, float z, float wv) {
    float x0f = floorf(x), y0f = floorf(y), z0f = floorf(z);
    float fx = x - x0f, fy = y - y0f, fz = z - z0f;
    int x0 = (int)x0f, y0 = (int)y0f, z0 = (int)z0f;
#pragma unroll
    for (int dz = 0; dz < 2; dz++) {
        int zi = z0 + dz;
        if (zi < 0 || zi >= DD) continue;
        float wz = (dz ? fz : 1.f - fz) * wv;
#pragma unroll
        for (int dy = 0; dy < 2; dy++) {
            int yi = y0 + dy;
            if (yi < 0 || yi >= DD) continue;
            float wzy = wz * (dy ? fy : 1.f - fy);
            int base = (zi << 14) + (yi << 7);
#pragma unroll
            for (int dx = 0; dx < 2; dx++) {
                int xi = x0 + dx;
                if (xi < 0 || xi >= DD) continue;
                atomicAdd(vol + base + xi, wzy * (dx ? fx : 1.f - fx));
            }
        }
    }
}

// ---------------- fused AtA: gather from src, scatter into dst ----------------
__global__ void k_AtA(const float* __restrict__ th, const float* __restrict__ src,
                      const float* __restrict__ psf, float* __restrict__ dst) {
    int i = blockIdx.x * blockDim.x + threadIdx.x;
    if (i >= NPIX) return;
    int w = i & 127, h = (i >> 7) & 127, n = i >> 14;
    const float* T = th + n * 12;
    float r00 = __ldg(T + 0), r01 = __ldg(T + 1), r02 = __ldg(T + 2),  t0 = __ldg(T + 3);
    float r10 = __ldg(T + 4), r11 = __ldg(T + 5), r12 = __ldg(T + 6),  t1 = __ldg(T + 7);
    float r20 = __ldg(T + 8), r21 = __ldg(T + 9), r22 = __ldg(T + 10), t2 = __ldg(T + 11);
    float u = (w - 63.5f) * 1.5f;
    float v = (h - 63.5f) * 1.5f;
    float qx = r00 * u + r01 * v + t0 + 63.5f;
    float qy = r10 * u + r11 * v + t1 + 63.5f;
    float qz = r20 * u + r21 * v + t2 + 63.5f;

    // pass 1: gather a = (A src)[pixel]
    float acc = 0.f;
    int k = 0;
    for (int iz = -1; iz <= 1; iz++) {
        float zx = qx + iz * r02, zy = qy + iz * r12, zz = qz + iz * r22;
        for (int iy = -1; iy <= 1; iy++) {
            float yx = zx + iy * r01, yy = zy + iy * r11, yz = zz + iy * r21;
            for (int ix = -1; ix <= 1; ix++, k++) {
                float x = yx + ix * r00, y = yy + ix * r10, z = yz + ix * r20;
                acc = fmaf(__ldg(psf + k), tri_gather(src, x, y, z), acc);
            }
        }
    }
    // pass 2: scatter a back (adjoint) into dst
    k = 0;
    for (int iz = -1; iz <= 1; iz++) {
        float zx = qx + iz * r02, zy = qy + iz * r12, zz = qz + iz * r22;
        for (int iy = -1; iy <= 1; iy++) {
            float yx = zx + iy * r01, yy = zy + iy * r11, yz = zz + iy * r21;
            for (int ix = -1; ix <= 1; ix++, k++) {
                float x = yx + ix * r00, y = yy + ix * r10, z = yz + ix * r20;
                tri_scatter(dst, x, y, z, acc * __ldg(psf + k));
            }
        }
    }
}

// ---------------- standalone At (for b = At(slices)) ----------------
__global__ void k_At(const float* __restrict__ th, const float* __restrict__ sl,
                     const float* __restrict__ psf, float* __restrict__ dst) {
    int i = blockIdx.x * blockDim.x + threadIdx.x;
    if (i >= NPIX) return;
    int w = i & 127, h = (i >> 7) & 127, n = i >> 14;
    const float* T = th + n * 12;
    float r00 = __ldg(T + 0), r01 = __ldg(T + 1), r02 = __ldg(T + 2),  t0 = __ldg(T + 3);
    float r10 = __ldg(T + 4), r11 = __ldg(T + 5), r12 = __ldg(T + 6),  t1 = __ldg(T + 7);
    float r20 = __ldg(T + 8), r21 = __ldg(T + 9), r22 = __ldg(T + 10), t2 = __ldg(T + 11);
    float u = (w - 63.5f) * 1.5f;
    float v = (h - 63.5f) * 1.5f;
    float qx = r00 * u + r01 * v + t0 + 63.5f;
    float qy = r10 * u + r11 * v + t1 + 63.5f;
    float qz = r20 * u + r21 * v + t2 + 63.5f;
    float s = __ldg(sl + i);
    int k = 0;
    for (int iz = -1; iz <= 1; iz++) {
        float zx = qx + iz * r02, zy = qy + iz * r12, zz = qz + iz * r22;
        for (int iy = -1; iy <= 1; iy++) {
            float yx = zx + iy * r01, yy = zy + iy * r11, yz = zz + iy * r21;
            for (int ix = -1; ix <= 1; ix++, k++) {
                float x = yx + ix * r00, y = yy + ix * r10, z = yz + ix * r20;
                tri_scatter(dst, x, y, z, s * __ldg(psf + k));
            }
        }
    }
}

// ---------------- host driver (graph-capturable: kernel launches only) ----------------
extern "C" void kernel_launch(void* const* d_in, const int* in_sizes, int n_in,
                              void* d_out, int out_size) {
    const float *theta = nullptr, *slices = nullptr, *vol0 = nullptr, *psf = nullptr;
    for (int i = 0; i < n_in; i++) {
        switch (in_sizes[i]) {
            case 192:   theta  = (const float*)d_in[i]; break;
            case NPIX:  slices = (const float*)d_in[i]; break;
            case VOL:   vol0   = (const float*)d_in[i]; break;
            case 27:    psf    = (const float*)d_in[i]; break;
        }
    }

    float *px, *pr, *pp, *pap, *pb, *ppart, *pscal;
    cudaGetSymbolAddress((void**)&px,    g_x);
    cudaGetSymbolAddress((void**)&pr,    g_r);
    cudaGetSymbolAddress((void**)&pp,    g_p);
    cudaGetSymbolAddress((void**)&pap,   g_Ap);
    cudaGetSymbolAddress((void**)&pb,    g_b);
    cudaGetSymbolAddress((void**)&ppart, g_part);
    cudaGetSymbolAddress((void**)&pscal, g_scal);

    const int VB = VOL / 256;    // 8192 blocks for volume-sized ops
    const int PB = NPIX / 256;   // 1024 blocks for pixel-sized ops

    // b = At(slices)
    k_zero<<<VB, 256>>>(pb, VOL);
    k_At<<<PB, 256>>>(theta, slices, psf, pb);

    // x = input volume
    k_copy<<<VB, 256>>>(px, vol0, VOL);

    // Ap = AtA(x0) ; r = b - Ap ; p = r ; rr = r.r
    k_zero<<<VB, 256>>>(pap, VOL);
    k_AtA<<<PB, 256>>>(theta, px, psf, pap);
    k_rp0<<<VB, 256>>>(pr, pp, pb, pap, VOL);
    k_dot<<<RED_BLOCKS, RED_THREADS>>>(pr, pr, ppart);
    k_final<<<1, RED_BLOCKS>>>(ppart, pscal, 0);

    for (int it = 0; it < CG_ITER; it++) {
        k_zero<<<VB, 256>>>(pap, VOL);
        k_AtA<<<PB, 256>>>(theta, pp, psf, pap);
        k_dot<<<RED_BLOCKS, RED_THREADS>>>(pp, pap, ppart);
        k_final<<<1, RED_BLOCKS>>>(ppart, pscal, 1);   // alpha = rr / p.Ap
        k_xr<<<VB, 256>>>(px, pr, pp, pap, pscal, VOL);
        k_dot<<<RED_BLOCKS, RED_THREADS>>>(pr, pr, ppart);
        k_final<<<1, RED_BLOCKS>>>(ppart, pscal, 2);   // beta = rr_new/rr ; rr = rr_new
        k_updp<<<VB, 256>>>(pp, pr, pscal, VOL);
    }

    k_relu<<<VB, 256>>>((float*)d_out, px, VOL);
    (void)out_size;
}

// round 2
// speedup vs baseline: 1.0060x; 1.0060x over previous
#include <cuda_runtime.h>
#include <math.h>

#define DD 128
#define VOL (DD*DD*DD)
#define NSL 16
#define NPIX (NSL*DD*DD)
#define CG_ITER 10

// scalar slots: [0..10] = rr[it], [16..25] = pAp[it], [31] = dummy sink
#define SC_RR   0
#define SC_PAP  16
#define SC_DUMP 31

__device__ float g_x[VOL];
__device__ float g_r[VOL];
__device__ float g_p[VOL];
__device__ float g_Ap[VOL];
__device__ float g_b[VOL];
__device__ float g_scal[32];

// ---------------- block reduction (sum) ----------------
__device__ __forceinline__ float block_sum(float v) {
    __shared__ float sh[8];
    int lane = threadIdx.x & 31, wid = threadIdx.x >> 5;
#pragma unroll
    for (int o = 16; o > 0; o >>= 1) v += __shfl_down_sync(0xffffffffu, v, o);
    if (lane == 0) sh[wid] = v;
    __syncthreads();
    if (wid == 0) {
        v = (lane < (blockDim.x >> 5)) ? sh[lane] : 0.f;
#pragma unroll
        for (int o = 4; o > 0; o >>= 1) v += __shfl_down_sync(0xffffffffu, v, o);
    }
    return v;  // valid in thread 0
}

// ---------------- init: zero b, Ap, scal ----------------
__global__ void k_init(float4* __restrict__ b4, float4* __restrict__ ap4) {
    int i = blockIdx.x * blockDim.x + threadIdx.x;
    float4 z = make_float4(0.f, 0.f, 0.f, 0.f);
    if (i < VOL / 4) { b4[i] = z; ap4[i] = z; }
    if (i < 32) g_scal[i] = 0.f;
}

// r = b - Ap ; p = r ; Ap = 0 ; rr[0] += r.r
__global__ void k_rp0(float4* __restrict__ r4, float4* __restrict__ p4,
                      const float4* __restrict__ b4, float4* __restrict__ ap4) {
    int i = blockIdx.x * blockDim.x + threadIdx.x;
    float s = 0.f;
    if (i < VOL / 4) {
        float4 b = b4[i], a = ap4[i];
        float4 v = make_float4(b.x - a.x, b.y - a.y, b.z - a.z, b.w - a.w);
        r4[i] = v; p4[i] = v;
        ap4[i] = make_float4(0.f, 0.f, 0.f, 0.f);
        s = v.x * v.x + v.y * v.y + v.z * v.z + v.w * v.w;
    }
    s = block_sum(s);
    if (threadIdx.x == 0) atomicAdd(&g_scal[SC_RR + 0], s);
}

// alpha = rr[it]/pAp[it] ; x = xin + a*p ; r -= a*Ap ; rr[it+1] += r.r
__global__ void k_xr(const float4* __restrict__ xin4, float4* __restrict__ xout4,
                     float4* __restrict__ r4, const float4* __restrict__ p4,
                     const float4* __restrict__ ap4, int it) {
    int i = blockIdx.x * blockDim.x + threadIdx.x;
    float s = 0.f;
    if (i < VOL / 4) {
        float a = g_scal[SC_RR + it] / g_scal[SC_PAP + it];
        float4 x = xin4[i], p = p4[i], ap = ap4[i], r = r4[i];
        x.x = fmaf(a, p.x, x.x); x.y = fmaf(a, p.y, x.y);
        x.z = fmaf(a, p.z, x.z); x.w = fmaf(a, p.w, x.w);
        r.x = fmaf(-a, ap.x, r.x); r.y = fmaf(-a, ap.y, r.y);
        r.z = fmaf(-a, ap.z, r.z); r.w = fmaf(-a, ap.w, r.w);
        xout4[i] = x; r4[i] = r;
        s = r.x * r.x + r.y * r.y + r.z * r.z + r.w * r.w;
    }
    s = block_sum(s);
    if (threadIdx.x == 0) atomicAdd(&g_scal[SC_RR + it + 1], s);
}

// beta = rr[it+1]/rr[it] ; p = r + beta*p ; Ap = 0
__global__ void k_updp(float4* __restrict__ p4, const float4* __restrict__ r4,
                       float4* __restrict__ ap4, int it) {
    int i = blockIdx.x * blockDim.x + threadIdx.x;
    if (i < VOL / 4) {
        float b = g_scal[SC_RR + it + 1] / g_scal[SC_RR + it];
        float4 p = p4[i], r = r4[i];
        p.x = fmaf(b, p.x, r.x); p.y = fmaf(b, p.y, r.y);
        p.z = fmaf(b, p.z, r.z); p.w = fmaf(b, p.w, r.w);
        p4[i] = p;
        ap4[i] = make_float4(0.f, 0.f, 0.f, 0.f);
    }
}

__global__ void k_relu(float4* __restrict__ o4, const float4* __restrict__ x4) {
    int i = blockIdx.x * blockDim.x + threadIdx.x;
    if (i < VOL / 4) {
        float4 x = x4[i];
        o4[i] = make_float4(fmaxf(x.x, 0.f), fmaxf(x.y, 0.f),
                            fmaxf(x.z, 0.f), fmaxf(x.w, 0.f));
    }
}

// ---------------- safe (boundary) trilinear ----------------
__device__ __forceinline__ float tri_gather_safe(const float* __restrict__ vol,
                                                 float x, float y, float z) {
    float x0f = floorf(x), y0f = floorf(y), z0f = floorf(z);
    float fx = x - x0f, fy = y - y0f, fz = z - z0f;
    int x0 = (int)x0f, y0 = (int)y0f, z0 = (int)z0f;
    float v = 0.f;
#pragma unroll
    for (int dz = 0; dz < 2; dz++) {
        int zi = z0 + dz;
        if (zi < 0 || zi >= DD) continue;
        float wz = dz ? fz : 1.f - fz;
#pragma unroll
        for (int dy = 0; dy < 2; dy++) {
            int yi = y0 + dy;
            if (yi < 0 || yi >= DD) continue;
            float wzy = wz * (dy ? fy : 1.f - fy);
            int base = (zi << 14) + (yi << 7);
#pragma unroll
            for (int dx = 0; dx < 2; dx++) {
                int xi = x0 + dx;
                if (xi < 0 || xi >= DD) continue;
                v = fmaf(wzy * (dx ? fx : 1.f - fx), __ldg(vol + base + xi), v);
            }
        }
    }
    return v;
}

__device__ __forceinline__ void tri_scatter_safe(float* __restrict__ vol,
                                                 float x, float y, float z, float wv) {
    float x0f = floorf(x), y0f = floorf(y), z0f = floorf(z);
    float fx = x - x0f, fy = y - y0f, fz = z - z0f;
    int x0 = (int)x0f, y0 = (int)y0f, z0 = (int)z0f;
#pragma unroll
    for (int dz = 0; dz < 2; dz++) {
        int zi = z0 + dz;
        if (zi < 0 || zi >= DD) continue;
        float wz = (dz ? fz : 1.f - fz) * wv;
#pragma unroll
        for (int dy = 0; dy < 2; dy++) {
            int yi = y0 + dy;
            if (yi < 0 || yi >= DD) continue;
            float wzy = wz * (dy ? fy : 1.f - fy);
            int base = (zi << 14) + (yi << 7);
#pragma unroll
            for (int dx = 0; dx < 2; dx++) {
                int xi = x0 + dx;
                if (xi < 0 || xi >= DD) continue;
                atomicAdd(vol + base + xi, wzy * (dx ? fx : 1.f - fx));
            }
        }
    }
}

// ---------------- fast (interior) trilinear ----------------
__device__ __forceinline__ float tri_gather_fast(const float* __restrict__ vol,
                                                 float x, float y, float z) {
    float x0f = floorf(x), y0f = floorf(y), z0f = floorf(z);
    float fx = x - x0f, fy = y - y0f, fz = z - z0f;
    int idx = (((int)z0f) << 14) + (((int)y0f) << 7) + (int)x0f;
    const float* p = vol + idx;
    float v000 = __ldg(p),         v001 = __ldg(p + 1);
    float v010 = __ldg(p + 128),   v011 = __ldg(p + 129);
    float v100 = __ldg(p + 16384), v101 = __ldg(p + 16385);
    float v110 = __ldg(p + 16512), v111 = __ldg(p + 16513);
    float c00 = fmaf(fx, v001 - v000, v000);
    float c01 = fmaf(fx, v011 - v010, v010);
    float c10 = fmaf(fx, v101 - v100, v100);
    float c11 = fmaf(fx, v111 - v110, v110);
    float c0 = fmaf(fy, c01 - c00, c00);
    float c1 = fmaf(fy, c11 - c10, c10);
    return fmaf(fz, c1 - c0, c0);
}

__device__ __forceinline__ void tri_scatter_fast(float* __restrict__ vol,
                                                 float x, float y, float z, float wv) {
    float x0f = floorf(x), y0f = floorf(y), z0f = floorf(z);
    float fx = x - x0f, fy = y - y0f, fz = z - z0f;
    int idx = (((int)z0f) << 14) + (((int)y0f) << 7) + (int)x0f;
    float* p = vol + idx;
    float wz1 = fz * wv, wz0 = wv - wz1;
    float w01 = fy * wz0, w00 = wz0 - w01;
    float w11 = fy * wz1, w10 = wz1 - w11;
    float t;
    t = fx * w00; atomicAdd(p,         w00 - t); atomicAdd(p + 1,     t);
    t = fx * w01; atomicAdd(p + 128,   w01 - t); atomicAdd(p + 129,   t);
    t = fx * w10; atomicAdd(p + 16384, w10 - t); atomicAdd(p + 16385, t);
    t = fx * w11; atomicAdd(p + 16512, w11 - t); atomicAdd(p + 16513, t);
}

// ---------------- shared setup: psf + transform + per-pixel geometry ----------------
struct Geo {
    float r00, r01, r02, r10, r11, r12, r20, r21, r22;
    float qx, qy, qz;
    int status;  // 0 = reject, 1 = interior fast, 2 = boundary slow
};

__device__ __forceinline__ Geo pixel_geo(const float* sT, int w, int h) {
    Geo g;
    g.r00 = sT[0]; g.r01 = sT[1]; g.r02 = sT[2];
    g.r10 = sT[4]; g.r11 = sT[5]; g.r12 = sT[6];
    g.r20 = sT[8]; g.r21 = sT[9]; g.r22 = sT[10];
    float u = (w - 63.5f) * 1.5f;
    float v = (h - 63.5f) * 1.5f;
    g.qx = g.r00 * u + g.r01 * v + sT[3]  + 63.5f;
    g.qy = g.r10 * u + g.r11 * v + sT[7]  + 63.5f;
    g.qz = g.r20 * u + g.r21 * v + sT[11] + 63.5f;
    float rx = fabsf(g.r00) + fabsf(g.r01) + fabsf(g.r02);
    float ry = fabsf(g.r10) + fabsf(g.r11) + fabsf(g.r12);
    float rz = fabsf(g.r20) + fabsf(g.r21) + fabsf(g.r22);
    bool rej = (g.qx + rx < -1.f) | (g.qx - rx >= 128.f) |
               (g.qy + ry < -1.f) | (g.qy - ry >= 128.f) |
               (g.qz + rz < -1.f) | (g.qz - rz >= 128.f);
    bool inter = (g.qx - rx >= 0.f) & (g.qx + rx < 127.f) &
                 (g.qy - ry >= 0.f) & (g.qy + ry < 127.f) &
                 (g.qz - rz >= 0.f) & (g.qz + rz < 127.f);
    g.status = rej ? 0 : (inter ? 1 : 2);
    return g;
}

// ---------------- fused AtA over one pixel tile ----------------
__global__ void __launch_bounds__(256)
k_AtA(const float* __restrict__ th, const float* __restrict__ src,
      const float* __restrict__ psf, float* __restrict__ dst,
      float* __restrict__ pap) {
    __shared__ float sp[27];
    __shared__ float sT[12];
    int tid = threadIdx.x;
    int b = blockIdx.x;
    int n = b >> 6;
    if (tid < 27) sp[tid] = psf[tid];
    if (tid < 12) sT[tid] = th[n * 12 + tid];
    __syncthreads();
    int tile = b & 63;
    int w = ((tile & 7) << 4) + (tid & 15);
    int h = ((tile >> 3) << 4) + (tid >> 4);

    Geo g = pixel_geo(sT, w, h);
    float acc = 0.f;
    if (g.status == 1) {
        int k = 0;
        for (int iz = -1; iz <= 1; iz++) {
            float zx = g.qx + iz * g.r02, zy = g.qy + iz * g.r12, zz = g.qz + iz * g.r22;
            for (int iy = -1; iy <= 1; iy++) {
                float yx = zx + iy * g.r01, yy = zy + iy * g.r11, yz = zz + iy * g.r21;
                for (int ix = -1; ix <= 1; ix++, k++)
                    acc = fmaf(sp[k], tri_gather_fast(src, yx + ix * g.r00,
                                                      yy + ix * g.r10, yz + ix * g.r20), acc);
            }
        }
        if (acc != 0.f) {
            k = 0;
            for (int iz = -1; iz <= 1; iz++) {
                float zx = g.qx + iz * g.r02, zy = g.qy + iz * g.r12, zz = g.qz + iz * g.r22;
                for (int iy = -1; iy <= 1; iy++) {
                    float yx = zx + iy * g.r01, yy = zy + iy * g.r11, yz = zz + iy * g.r21;
                    for (int ix = -1; ix <= 1; ix++, k++)
                        tri_scatter_fast(dst, yx + ix * g.r00, yy + ix * g.r10,
                                         yz + ix * g.r20, acc * sp[k]);
                }
            }
        }
    } else if (g.status == 2) {
        int k = 0;
        for (int iz = -1; iz <= 1; iz++) {
            float zx = g.qx + iz * g.r02, zy = g.qy + iz * g.r12, zz = g.qz + iz * g.r22;
            for (int iy = -1; iy <= 1; iy++) {
                float yx = zx + iy * g.r01, yy = zy + iy * g.r11, yz = zz + iy * g.r21;
                for (int ix = -1; ix <= 1; ix++, k++)
                    acc = fmaf(sp[k], tri_gather_safe(src, yx + ix * g.r00,
                                                      yy + ix * g.r10, yz + ix * g.r20), acc);
            }
        }
        if (acc != 0.f) {
            k = 0;
            for (int iz = -1; iz <= 1; iz++) {
                float zx = g.qx + iz * g.r02, zy = g.qy + iz * g.r12, zz = g.qz + iz * g.r22;
                for (int iy = -1; iy <= 1; iy++) {
                    float yx = zx + iy * g.r01, yy = zy + iy * g.r11, yz = zz + iy * g.r21;
                    for (int ix = -1; ix <= 1; ix++, k++)
                        tri_scatter_safe(dst, yx + ix * g.r00, yy + ix * g.r10,
                                         yz + ix * g.r20, acc * sp[k]);
                }
            }
        }
    }
    float s = block_sum(acc * acc);
    if (tid == 0) atomicAdd(pap, s);
}

// ---------------- standalone At (b = At slices) ----------------
__global__ void __launch_bounds__(256)
k_At(const float* __restrict__ th, const float* __restrict__ sl,
     const float* __restrict__ psf, float* __restrict__ dst) {
    __shared__ float sp[27];
    __shared__ float sT[12];
    int tid = threadIdx.x;
    int b = blockIdx.x;
    int n = b >> 6;
    if (tid < 27) sp[tid] = psf[tid];
    if (tid < 12) sT[tid] = th[n * 12 + tid];
    __syncthreads();
    int tile = b & 63;
    int w = ((tile & 7) << 4) + (tid & 15);
    int h = ((tile >> 3) << 4) + (tid >> 4);

    Geo g = pixel_geo(sT, w, h);
    if (g.status == 0) return;
    float s = __ldg(sl + (n << 14) + (h << 7) + w);
    if (s == 0.f) return;
    int k = 0;
    if (g.status == 1) {
        for (int iz = -1; iz <= 1; iz++) {
            float zx = g.qx + iz * g.r02, zy = g.qy + iz * g.r12, zz = g.qz + iz * g.r22;
            for (int iy = -1; iy <= 1; iy++) {
                float yx = zx + iy * g.r01, yy = zy + iy * g.r11, yz = zz + iy * g.r21;
                for (int ix = -1; ix <= 1; ix++, k++)
                    tri_scatter_fast(dst, yx + ix * g.r00, yy + ix * g.r10,
                                     yz + ix * g.r20, s * sp[k]);
            }
        }
    } else {
        for (int iz = -1; iz <= 1; iz++) {
            float zx = g.qx + iz * g.r02, zy = g.qy + iz * g.r12, zz = g.qz + iz * g.r22;
            for (int iy = -1; iy <= 1; iy++) {
                float yx = zx + iy * g.r01, yy = zy + iy * g.r11, yz = zz + iy * g.r21;
                for (int ix = -1; ix <= 1; ix++, k++)
                    tri_scatter_safe(dst, yx + ix * g.r00, yy + ix * g.r10,
                                     yz + ix * g.r20, s * sp[k]);
            }
        }
    }
}

// ---------------- host driver ----------------
extern "C" void kernel_launch(void* const* d_in, const int* in_sizes, int n_in,
                              void* d_out, int out_size) {
    const float *theta = nullptr, *slices = nullptr, *vol0 = nullptr, *psf = nullptr;
    for (int i = 0; i < n_in; i++) {
        switch (in_sizes[i]) {
            case 192:   theta  = (const float*)d_in[i]; break;
            case NPIX:  slices = (const float*)d_in[i]; break;
            case VOL:   vol0   = (const float*)d_in[i]; break;
            case 27:    psf    = (const float*)d_in[i]; break;
        }
    }

    float *px, *pr, *pp, *pap, *pb, *pscal;
    cudaGetSymbolAddress((void**)&px,    g_x);
    cudaGetSymbolAddress((void**)&pr,    g_r);
    cudaGetSymbolAddress((void**)&pp,    g_p);
    cudaGetSymbolAddress((void**)&pap,   g_Ap);
    cudaGetSymbolAddress((void**)&pb,    g_b);
    cudaGetSymbolAddress((void**)&pscal, g_scal);

    const int V4B = (VOL / 4) / 256;   // 2048 blocks for float4 volume ops
    const int PB  = NPIX / 256;        // 1024 blocks for pixel ops

    // init: zero b, Ap, scal
    k_init<<<V4B, 256>>>((float4*)pb, (float4*)pap);
    // b = At(slices)
    k_At<<<PB, 256>>>(theta, slices, psf, pb);
    // Ap = AtA(x0)  (x0 = input volume directly)
    k_AtA<<<PB, 256>>>(theta, vol0, psf, pap, pscal + SC_DUMP);
    // r = b - Ap ; p = r ; rr[0] ; Ap = 0
    k_rp0<<<V4B, 256>>>((float4*)pr, (float4*)pp, (float4*)pb, (float4*)pap);

    for (int it = 0; it < CG_ITER; it++) {
        k_AtA<<<PB, 256>>>(theta, pp, psf, pap, pscal + SC_PAP + it);
        const float* xin = (it == 0) ? vol0 : px;
        k_xr<<<V4B, 256>>>((const float4*)xin, (float4*)px, (float4*)pr,
                           (const float4*)pp, (const float4*)pap, it);
        k_updp<<<V4B, 256>>>((float4*)pp, (const float4*)pr, (float4*)pap, it);
    }

    k_relu<<<V4B, 256>>>((float4*)d_out, (const float4*)px);
    (void)out_size;
}

// round 4
// speedup vs baseline: 1.1387x; 1.1319x over previous
#include <cuda_runtime.h>
#include <math.h>

#define DD 128
#define VOL (DD*DD*DD)
#define NSL 16
#define NPIX (NSL*DD*DD)
#define CG_ITER 10

#define SC_RR   0
#define SC_PAP  16
#define SC_DUMP 31

#define TPB 128            // threads per heavy block (16x8 pixel tile)
#define PCELLS 125         // 5x5x5 private footprint
#define HEAVY_SMEM (PCELLS * TPB * 4)

__device__ float g_x[VOL];
__device__ float g_r[VOL];
__device__ float g_p[VOL];
__device__ float g_Ap[VOL];
__device__ float g_b[VOL];
__device__ float g_scal[32];

// ---------------- block reduction (sum) ----------------
__device__ __forceinline__ float block_sum(float v) {
    __shared__ float sh[8];
    int lane = threadIdx.x & 31, wid = threadIdx.x >> 5;
#pragma unroll
    for (int o = 16; o > 0; o >>= 1) v += __shfl_down_sync(0xffffffffu, v, o);
    if (lane == 0) sh[wid] = v;
    __syncthreads();
    if (wid == 0) {
        v = (lane < (blockDim.x >> 5)) ? sh[lane] : 0.f;
#pragma unroll
        for (int o = 4; o > 0; o >>= 1) v += __shfl_down_sync(0xffffffffu, v, o);
    }
    return v;  // valid in thread 0
}

// ---------------- small vector kernels ----------------
__global__ void k_init(float4* __restrict__ b4, float4* __restrict__ ap4) {
    int i = blockIdx.x * blockDim.x + threadIdx.x;
    float4 z = make_float4(0.f, 0.f, 0.f, 0.f);
    if (i < VOL / 4) { b4[i] = z; ap4[i] = z; }
    if (i < 32) g_scal[i] = 0.f;
}

__global__ void k_rp0(float4* __restrict__ r4, float4* __restrict__ p4,
                      const float4* __restrict__ b4, float4* __restrict__ ap4) {
    int i = blockIdx.x * blockDim.x + threadIdx.x;
    float s = 0.f;
    if (i < VOL / 4) {
        float4 b = b4[i], a = ap4[i];
        float4 v = make_float4(b.x - a.x, b.y - a.y, b.z - a.z, b.w - a.w);
        r4[i] = v; p4[i] = v;
        ap4[i] = make_float4(0.f, 0.f, 0.f, 0.f);
        s = v.x * v.x + v.y * v.y + v.z * v.z + v.w * v.w;
    }
    s = block_sum(s);
    if (threadIdx.x == 0) atomicAdd(&g_scal[SC_RR + 0], s);
}

__global__ void k_xr(const float4* __restrict__ xin4, float4* __restrict__ xout4,
                     float4* __restrict__ r4, const float4* __restrict__ p4,
                     const float4* __restrict__ ap4, int it) {
    int i = blockIdx.x * blockDim.x + threadIdx.x;
    float s = 0.f;
    if (i < VOL / 4) {
        float a = g_scal[SC_RR + it] / g_scal[SC_PAP + it];
        float4 x = xin4[i], p = p4[i], ap = ap4[i], r = r4[i];
        x.x = fmaf(a, p.x, x.x); x.y = fmaf(a, p.y, x.y);
        x.z = fmaf(a, p.z, x.z); x.w = fmaf(a, p.w, x.w);
        r.x = fmaf(-a, ap.x, r.x); r.y = fmaf(-a, ap.y, r.y);
        r.z = fmaf(-a, ap.z, r.z); r.w = fmaf(-a, ap.w, r.w);
        xout4[i] = x; r4[i] = r;
        s = r.x * r.x + r.y * r.y + r.z * r.z + r.w * r.w;
    }
    s = block_sum(s);
    if (threadIdx.x == 0) atomicAdd(&g_scal[SC_RR + it + 1], s);
}

__global__ void k_updp(float4* __restrict__ p4, const float4* __restrict__ r4,
                       float4* __restrict__ ap4, int it) {
    int i = blockIdx.x * blockDim.x + threadIdx.x;
    if (i < VOL / 4) {
        float b = g_scal[SC_RR + it + 1] / g_scal[SC_RR + it];
        float4 p = p4[i], r = r4[i];
        p.x = fmaf(b, p.x, r.x); p.y = fmaf(b, p.y, r.y);
        p.z = fmaf(b, p.z, r.z); p.w = fmaf(b, p.w, r.w);
        p4[i] = p;
        ap4[i] = make_float4(0.f, 0.f, 0.f, 0.f);
    }
}

__global__ void k_relu(float4* __restrict__ o4, const float4* __restrict__ x4) {
    int i = blockIdx.x * blockDim.x + threadIdx.x;
    if (i < VOL / 4) {
        float4 x = x4[i];
        o4[i] = make_float4(fmaxf(x.x, 0.f), fmaxf(x.y, 0.f),
                            fmaxf(x.z, 0.f), fmaxf(x.w, 0.f));
    }
}

// ---------------- gathers ----------------
__device__ __forceinline__ float tri_gather_safe(const float* __restrict__ vol,
                                                 float x, float y, float z) {
    float x0f = floorf(x), y0f = floorf(y), z0f = floorf(z);
    float fx = x - x0f, fy = y - y0f, fz = z - z0f;
    int x0 = (int)x0f, y0 = (int)y0f, z0 = (int)z0f;
    float v = 0.f;
#pragma unroll
    for (int dz = 0; dz < 2; dz++) {
        int zi = z0 + dz;
        if (zi < 0 || zi >= DD) continue;
        float wz = dz ? fz : 1.f - fz;
#pragma unroll
        for (int dy = 0; dy < 2; dy++) {
            int yi = y0 + dy;
            if (yi < 0 || yi >= DD) continue;
            float wzy = wz * (dy ? fy : 1.f - fy);
            int base = (zi << 14) + (yi << 7);
#pragma unroll
            for (int dx = 0; dx < 2; dx++) {
                int xi = x0 + dx;
                if (xi < 0 || xi >= DD) continue;
                v = fmaf(wzy * (dx ? fx : 1.f - fx), __ldg(vol + base + xi), v);
            }
        }
    }
    return v;
}

__device__ __forceinline__ float tri_gather_fast(const float* __restrict__ vol,
                                                 float x, float y, float z) {
    float x0f = floorf(x), y0f = floorf(y), z0f = floorf(z);
    float fx = x - x0f, fy = y - y0f, fz = z - z0f;
    int idx = (((int)z0f) << 14) + (((int)y0f) << 7) + (int)x0f;
    const float* p = vol + idx;
    float v000 = __ldg(p),         v001 = __ldg(p + 1);
    float v010 = __ldg(p + 128),   v011 = __ldg(p + 129);
    float v100 = __ldg(p + 16384), v101 = __ldg(p + 16385);
    float v110 = __ldg(p + 16512), v111 = __ldg(p + 16513);
    float c00 = fmaf(fx, v001 - v000, v000);
    float c01 = fmaf(fx, v011 - v010, v010);
    float c10 = fmaf(fx, v101 - v100, v100);
    float c11 = fmaf(fx, v111 - v110, v110);
    float c0 = fmaf(fy, c01 - c00, c00);
    float c1 = fmaf(fy, c11 - c10, c10);
    return fmaf(fz, c1 - c0, c0);
}

// direct global-atomic scatter (fallback only)
__device__ __forceinline__ void tri_scatter_safe(float* __restrict__ vol,
                                                 float x, float y, float z, float wv) {
    float x0f = floorf(x), y0f = floorf(y), z0f = floorf(z);
    float fx = x - x0f, fy = y - y0f, fz = z - z0f;
    int x0 = (int)x0f, y0 = (int)y0f, z0 = (int)z0f;
#pragma unroll
    for (int dz = 0; dz < 2; dz++) {
        int zi = z0 + dz;
        if (zi < 0 || zi >= DD) continue;
        float wz = (dz ? fz : 1.f - fz) * wv;
#pragma unroll
        for (int dy = 0; dy < 2; dy++) {
            int yi = y0 + dy;
            if (yi < 0 || yi >= DD) continue;
            float wzy = wz * (dy ? fy : 1.f - fy);
            int base = (zi << 14) + (yi << 7);
#pragma unroll
            for (int dx = 0; dx < 2; dx++) {
                int xi = x0 + dx;
                if (xi < 0 || xi >= DD) continue;
                atomicAdd(vol + base + xi, wzy * (dx ? fx : 1.f - fx));
            }
        }
    }
}

// private-SMEM scatter: accumulate one tap's 8 corners into thread-private tile
__device__ __forceinline__ void tri_scatter_priv(float* __restrict__ priv,
                                                 int ox, int oy, int oz,
                                                 float x, float y, float z, float wv) {
    float x0f = floorf(x), y0f = floorf(y), z0f = floorf(z);
    float fx = x - x0f, fy = y - y0f, fz = z - z0f;
    int c = (((int)z0f - oz) * 5 + ((int)y0f - oy)) * 5 + ((int)x0f - ox);
    float wz1 = fz * wv, wz0 = wv - wz1;
    float w01 = fy * wz0, w00 = wz0 - w01;
    float w11 = fy * wz1, w10 = wz1 - w11;
    float t;
    t = fx * w00; priv[c * TPB]        += w00 - t; priv[(c + 1) * TPB]  += t;
    t = fx * w01; priv[(c + 5) * TPB]  += w01 - t; priv[(c + 6) * TPB]  += t;
    t = fx * w10; priv[(c + 25) * TPB] += w10 - t; priv[(c + 26) * TPB] += t;
    t = fx * w11; priv[(c + 30) * TPB] += w11 - t; priv[(c + 31) * TPB] += t;
}

// ---------------- geometry ----------------
struct Geo {
    float r00, r01, r02, r10, r11, r12, r20, r21, r22;
    float qx, qy, qz;
    float rx, ry, rz;
    int status;  // 0 reject, 1 interior(fast gather), 2 boundary(safe gather), 3 fallback
};

__device__ __forceinline__ Geo pixel_geo(const float* sT, int w, int h) {
    Geo g;
    g.r00 = sT[0]; g.r01 = sT[1]; g.r02 = sT[2];
    g.r10 = sT[4]; g.r11 = sT[5]; g.r12 = sT[6];
    g.r20 = sT[8]; g.r21 = sT[9]; g.r22 = sT[10];
    float u = (w - 63.5f) * 1.5f;
    float v = (h - 63.5f) * 1.5f;
    g.qx = g.r00 * u + g.r01 * v + sT[3]  + 63.5f;
    g.qy = g.r10 * u + g.r11 * v + sT[7]  + 63.5f;
    g.qz = g.r20 * u + g.r21 * v + sT[11] + 63.5f;
    g.rx = fabsf(g.r00) + fabsf(g.r01) + fabsf(g.r02);
    g.ry = fabsf(g.r10) + fabsf(g.r11) + fabsf(g.r12);
    g.rz = fabsf(g.r20) + fabsf(g.r21) + fabsf(g.r22);
    bool rej = (g.qx + g.rx < -1.f) | (g.qx - g.rx >= 128.f) |
               (g.qy + g.ry < -1.f) | (g.qy - g.ry >= 128.f) |
               (g.qz + g.rz < -1.f) | (g.qz - g.rz >= 128.f);
    bool inter = (g.qx - g.rx >= 0.f) & (g.qx + g.rx < 127.f) &
                 (g.qy - g.ry >= 0.f) & (g.qy + g.ry < 127.f) &
                 (g.qz - g.rz >= 0.f) & (g.qz + g.rz < 127.f);
    bool fits = (g.rx < 1.49f) & (g.ry < 1.49f) & (g.rz < 1.49f);
    g.status = rej ? 0 : (fits ? (inter ? 1 : 2) : 3);
    return g;
}

// flush private tile to global with bounds check, skipping zeros
__device__ __forceinline__ void flush_priv(const float* __restrict__ priv,
                                           float* __restrict__ dst,
                                           int ox, int oy, int oz) {
#pragma unroll 5
    for (int c = 0; c < PCELLS; c++) {
        float v = priv[c * TPB];
        if (v != 0.f) {
            int x = ox + (c % 5), y = oy + ((c / 5) % 5), z = oz + (c / 25);
            if ((unsigned)x < DD && (unsigned)y < DD && (unsigned)z < DD)
                atomicAdd(dst + (z << 14) + (y << 7) + x, v);
        }
    }
}

// ---------------- fused AtA ----------------
__global__ void __launch_bounds__(TPB)
k_AtA(const float* __restrict__ th, const float* __restrict__ src,
      const float* __restrict__ psf, float* __restrict__ dst,
      float* __restrict__ pap) {
    extern __shared__ float scr[];
    __shared__ float sp[27];
    __shared__ float sT[12];
    int tid = threadIdx.x;
    int b = blockIdx.x;
    int n = b >> 7;                      // 128 blocks per slice
    if (tid < 27) sp[tid] = psf[tid];
    if (tid < 12) sT[tid] = th[n * 12 + tid];
    __syncthreads();
    int tile = b & 127;                  // 8 x-tiles * 16 y-tiles
    int w = ((tile & 7) << 4) + (tid & 15);
    int h = ((tile >> 3) << 3) + (tid >> 4);

    Geo g = pixel_geo(sT, w, h);
    float acc = 0.f;
    if (g.status == 1) {
        int k = 0;
        for (int iz = -1; iz <= 1; iz++) {
            float zx = g.qx + iz * g.r02, zy = g.qy + iz * g.r12, zz = g.qz + iz * g.r22;
            for (int iy = -1; iy <= 1; iy++) {
                float yx = zx + iy * g.r01, yy = zy + iy * g.r11, yz = zz + iy * g.r21;
                for (int ix = -1; ix <= 1; ix++, k++)
                    acc = fmaf(sp[k], tri_gather_fast(src, yx + ix * g.r00,
                                                      yy + ix * g.r10, yz + ix * g.r20), acc);
            }
        }
    } else if (g.status >= 2) {
        int k = 0;
        for (int iz = -1; iz <= 1; iz++) {
            float zx = g.qx + iz * g.r02, zy = g.qy + iz * g.r12, zz = g.qz + iz * g.r22;
            for (int iy = -1; iy <= 1; iy++) {
                float yx = zx + iy * g.r01, yy = zy + iy * g.r11, yz = zz + iy * g.r21;
                for (int ix = -1; ix <= 1; ix++, k++)
                    acc = fmaf(sp[k], tri_gather_safe(src, yx + ix * g.r00,
                                                      yy + ix * g.r10, yz + ix * g.r20), acc);
            }
        }
    }
    float s = block_sum(acc * acc);
    if (tid == 0) atomicAdd(pap, s);

    if (acc == 0.f) return;
    if (g.status == 3) {   // ultra-safe fallback (never expected)
        int k = 0;
        for (int iz = -1; iz <= 1; iz++) {
            float zx = g.qx + iz * g.r02, zy = g.qy + iz * g.r12, zz = g.qz + iz * g.r22;
            for (int iy = -1; iy <= 1; iy++) {
                float yx = zx + iy * g.r01, yy = zy + iy * g.r11, yz = zz + iy * g.r21;
                for (int ix = -1; ix <= 1; ix++, k++)
                    tri_scatter_safe(dst, yx + ix * g.r00, yy + ix * g.r10,
                                     yz + ix * g.r20, acc * sp[k]);
            }
        }
        return;
    }
    // private-SMEM accumulation
    float* priv = scr + tid;
#pragma unroll 5
    for (int c = 0; c < PCELLS; c++) priv[c * TPB] = 0.f;
    int ox = (int)floorf(g.qx - g.rx);
    int oy = (int)floorf(g.qy - g.ry);
    int oz = (int)floorf(g.qz - g.rz);
    int k = 0;
    for (int iz = -1; iz <= 1; iz++) {
        float zx = g.qx + iz * g.r02, zy = g.qy + iz * g.r12, zz = g.qz + iz * g.r22;
        for (int iy = -1; iy <= 1; iy++) {
            float yx = zx + iy * g.r01, yy = zy + iy * g.r11, yz = zz + iy * g.r21;
            for (int ix = -1; ix <= 1; ix++, k++)
                tri_scatter_priv(priv, ox, oy, oz, yx + ix * g.r00,
                                 yy + ix * g.r10, yz + ix * g.r20, acc * sp[k]);
        }
    }
    flush_priv(priv, dst, ox, oy, oz);
}

// ---------------- standalone At (b = At slices) ----------------
__global__ void __launch_bounds__(TPB)
k_At(const float* __restrict__ th, const float* __restrict__ sl,
     const float* __restrict__ psf, float* __restrict__ dst) {
    extern __shared__ float scr[];
    __shared__ float sp[27];
    __shared__ float sT[12];
    int tid = threadIdx.x;
    int b = blockIdx.x;
    int n = b >> 7;
    if (tid < 27) sp[tid] = psf[tid];
    if (tid < 12) sT[tid] = th[n * 12 + tid];
    __syncthreads();
    int tile = b & 127;
    int w = ((tile & 7) << 4) + (tid & 15);
    int h = ((tile >> 3) << 3) + (tid >> 4);

    Geo g = pixel_geo(sT, w, h);
    if (g.status == 0) return;
    float s = __ldg(sl + (n << 14) + (h << 7) + w);
    if (s == 0.f) return;
    if (g.status == 3) {
        int k = 0;
        for (int iz = -1; iz <= 1; iz++) {
            float zx = g.qx + iz * g.r02, zy = g.qy + iz * g.r12, zz = g.qz + iz * g.r22;
            for (int iy = -1; iy <= 1; iy++) {
                float yx = zx + iy * g.r01, yy = zy + iy * g.r11, yz = zz + iy * g.r21;
                for (int ix = -1; ix <= 1; ix++, k++)
                    tri_scatter_safe(dst, yx + ix * g.r00, yy + ix * g.r10,
                                     yz + ix * g.r20, s * sp[k]);
            }
        }
        return;
    }
    float* priv = scr + tid;
#pragma unroll 5
    for (int c = 0; c < PCELLS; c++) priv[c * TPB] = 0.f;
    int ox = (int)floorf(g.qx - g.rx);
    int oy = (int)floorf(g.qy - g.ry);
    int oz = (int)floorf(g.qz - g.rz);
    int k = 0;
    for (int iz = -1; iz <= 1; iz++) {
        float zx = g.qx + iz * g.r02, zy = g.qy + iz * g.r12, zz = g.qz + iz * g.r22;
        for (int iy = -1; iy <= 1; iy++) {
            float yx = zx + iy * g.r01, yy = zy + iy * g.r11, yz = zz + iy * g.r21;
            for (int ix = -1; ix <= 1; ix++, k++)
                tri_scatter_priv(priv, ox, oy, oz, yx + ix * g.r00,
                                 yy + ix * g.r10, yz + ix * g.r20, s * sp[k]);
        }
    }
    flush_priv(priv, dst, ox, oy, oz);
}

// ---------------- host driver ----------------
extern "C" void kernel_launch(void* const* d_in, const int* in_sizes, int n_in,
                              void* d_out, int out_size) {
    const float *theta = nullptr, *slices = nullptr, *vol0 = nullptr, *psf = nullptr;
    for (int i = 0; i < n_in; i++) {
        switch (in_sizes[i]) {
            case 192:   theta  = (const float*)d_in[i]; break;
            case NPIX:  slices = (const float*)d_in[i]; break;
            case VOL:   vol0   = (const float*)d_in[i]; break;
            case 27:    psf    = (const float*)d_in[i]; break;
        }
    }

    float *px, *pr, *pp, *pap, *pb, *pscal;
    cudaGetSymbolAddress((void**)&px,    g_x);
    cudaGetSymbolAddress((void**)&pr,    g_r);
    cudaGetSymbolAddress((void**)&pp,    g_p);
    cudaGetSymbolAddress((void**)&pap,   g_Ap);
    cudaGetSymbolAddress((void**)&pb,    g_b);
    cudaGetSymbolAddress((void**)&pscal, g_scal);

    cudaFuncSetAttribute(k_AtA, cudaFuncAttributeMaxDynamicSharedMemorySize, HEAVY_SMEM);
    cudaFuncSetAttribute(k_At,  cudaFuncAttributeMaxDynamicSharedMemorySize, HEAVY_SMEM);

    const int V4B = (VOL / 4) / 256;   // 2048 blocks for float4 volume ops
    const int PB  = NPIX / TPB;        // 2048 blocks for pixel ops (16x8 tiles)

    k_init<<<V4B, 256>>>((float4*)pb, (float4*)pap);
    k_At<<<PB, TPB, HEAVY_SMEM>>>(theta, slices, psf, pb);
    k_AtA<<<PB, TPB, HEAVY_SMEM>>>(theta, vol0, psf, pap, pscal + SC_DUMP);
    k_rp0<<<V4B, 256>>>((float4*)pr, (float4*)pp, (float4*)pb, (float4*)pap);

    for (int it = 0; it < CG_ITER; it++) {
        k_AtA<<<PB, TPB, HEAVY_SMEM>>>(theta, pp, psf, pap, pscal + SC_PAP + it);
        const float* xin = (it == 0) ? vol0 : px;
        k_xr<<<V4B, 256>>>((const float4*)xin, (float4*)px, (float4*)pr,
                           (const float4*)pp, (const float4*)pap, it);
        k_updp<<<V4B, 256>>>((float4*)pp, (const float4*)pr, (float4*)pap, it);
    }

    k_relu<<<V4B, 256>>>((float4*)d_out, (const float4*)px);
    (void)out_size;
}